// round 6
// baseline (speedup 1.0000x reference)
#include <cuda_runtime.h>

#define EPS 1e-5f

// ---- scratch (static device globals; no allocation at runtime) ----
static __device__ float g_q[16 * 512 * 1024];   // [b, h*64+d, i]
static __device__ float g_k[16 * 512 * 1024];   // [b, h*64+d, j]
static __device__ float g_v[16 * 512 * 1024];   // [b, h*64+d, j]
static __device__ float g_o[16 * 1024 * 512];   // [b, i, h*64+d]

__device__ __forceinline__ float hswish(float x) {
    return x * __saturatef((x + 3.0f) * (1.0f / 6.0f));
}

// ============================================================================
// Kernel 1: fused Q/K/V projection GEMM + BN epilogue.
// out[b, o, p] = bn(sum_c W[o,c] * X[b,c,p]),  X: [16,256,1024], W: [512,256]
// 64(o) x 64(p) tile, 128 threads, 8x4 frags. gridDim.z selects (which, b).
// ============================================================================
__global__ __launch_bounds__(128) void proj_kernel(
    const float* __restrict__ X,
    const float* __restrict__ Wq, const float* __restrict__ Wk, const float* __restrict__ Wv,
    const float* __restrict__ gq, const float* __restrict__ bq,
    const float* __restrict__ mq, const float* __restrict__ vq,
    const float* __restrict__ gk, const float* __restrict__ bk,
    const float* __restrict__ mk, const float* __restrict__ vk,
    const float* __restrict__ gv, const float* __restrict__ bv,
    const float* __restrict__ mv, const float* __restrict__ vv)
{
    __shared__ float Ws[16][68];
    __shared__ float Xs[16][68];

    const int which = blockIdx.z >> 4;       // 0=q, 1=k, 2=v
    const int b     = blockIdx.z & 15;
    const float* W   = (which == 0) ? Wq : (which == 1) ? Wk : Wv;
    const float* gam = (which == 0) ? gq : (which == 1) ? gk : gv;
    const float* bet = (which == 0) ? bq : (which == 1) ? bk : bv;
    const float* mu  = (which == 0) ? mq : (which == 1) ? mk : mv;
    const float* var = (which == 0) ? vq : (which == 1) ? vk : vv;
    float* outbuf    = (which == 0) ? g_q : (which == 1) ? g_k : g_v;

    const int o0 = blockIdx.y * 64;
    const int p0 = blockIdx.x * 64;
    const int tid = threadIdx.x;
    const int tx = tid & 15;    // p columns (4 each)
    const int ty = tid >> 4;    // o rows    (8 each)
    const float* Xb = X + b * 256 * 1024;

    float acc[8][4];
#pragma unroll
    for (int r = 0; r < 8; r++)
#pragma unroll
        for (int c = 0; c < 4; c++) acc[r][c] = 0.f;

    for (int kk = 0; kk < 256; kk += 16) {
        {   // Ws[k][o]
            int o_l = tid >> 1;
            int k8  = (tid & 1) * 8;
#pragma unroll
            for (int jj = 0; jj < 2; jj++) {
                float4 w4 = *(const float4*)(W + (o0 + o_l) * 256 + kk + k8 + jj * 4);
                Ws[k8 + jj * 4 + 0][o_l] = w4.x;
                Ws[k8 + jj * 4 + 1][o_l] = w4.y;
                Ws[k8 + jj * 4 + 2][o_l] = w4.z;
                Ws[k8 + jj * 4 + 3][o_l] = w4.w;
            }
        }
        {   // Xs[k][p]
            int k_l = tid >> 3;
            int p8  = (tid & 7) * 8;
#pragma unroll
            for (int jj = 0; jj < 2; jj++)
                *(float4*)&Xs[k_l][p8 + jj * 4] =
                    *(const float4*)(Xb + (kk + k_l) * 1024 + p0 + p8 + jj * 4);
        }
        __syncthreads();
#pragma unroll
        for (int k = 0; k < 16; k++) {
            float4 a0 = *(const float4*)&Ws[k][ty * 8];
            float4 a1 = *(const float4*)&Ws[k][ty * 8 + 4];
            float4 b0 = *(const float4*)&Xs[k][tx * 4];
            float a[8] = {a0.x, a0.y, a0.z, a0.w, a1.x, a1.y, a1.z, a1.w};
            float bb[4] = {b0.x, b0.y, b0.z, b0.w};
#pragma unroll
            for (int r = 0; r < 8; r++)
#pragma unroll
                for (int c = 0; c < 4; c++)
                    acc[r][c] = fmaf(a[r], bb[c], acc[r][c]);
        }
        __syncthreads();
    }
#pragma unroll
    for (int r = 0; r < 8; r++) {
        int o = o0 + ty * 8 + r;
        float s = gam[o] * rsqrtf(var[o] + EPS);
        float t = bet[o] - mu[o] * s;
        float4 v;
        v.x = fmaf(acc[r][0], s, t);
        v.y = fmaf(acc[r][1], s, t);
        v.z = fmaf(acc[r][2], s, t);
        v.w = fmaf(acc[r][3], s, t);
        *(float4*)(outbuf + (b * 512 + o) * 1024 + p0 + tx * 4) = v;
    }
}

// ============================================================================
// Kernel 2: flash attention per (b,h), 64 query rows per block, online softmax.
// S[i,j] = 0.125 * sum_d Q[i,d]K[j,d] + 8 * emb[idx(i,j), h]
//   where idx(i,j) = |xi-xj|*32 + |yi-yj|, (x,y) = (pos>>5, pos&31)
// O[i,d] = softmax(S) @ V.  Writes g_o[b, i, h*64+d].
// 128 threads, 8(i) x 4 frags.
// ============================================================================
__global__ __launch_bounds__(128) void attn_kernel(const float* __restrict__ emb)
{
    extern __shared__ float smn[];
    float (*Qs)[68] = (float(*)[68])(smn);
    float (*Ks)[68] = (float(*)[68])(smn + 64 * 68);
    float (*Vs)[68] = (float(*)[68])(smn + 2 * 64 * 68);   // Vs[j][d]
    float (*Ps)[68] = (float(*)[68])(smn + 3 * 64 * 68);   // Ps[j][i]
    float* semb = smn + 4 * 64 * 68;                       // 1024 floats

    const int bh = blockIdx.y;
    const int b = bh >> 3, h = bh & 7;
    const int i0 = blockIdx.x * 64;
    const int tid = threadIdx.x;
    const int tx = tid & 15;    // j (or d) columns, 4 each
    const int ty = tid >> 4;    // i rows, 8 each

    const float* Qg = g_q + (b * 512 + h * 64) * 1024;
    const float* Kg = g_k + (b * 512 + h * 64) * 1024;
    const float* Vg = g_v + (b * 512 + h * 64) * 1024;

    for (int i = tid; i < 1024; i += 128)
        semb[i] = emb[i * 8 + h] * 8.0f;

    {   // Qs[d][i]
        int d_l = tid >> 1;
        int ih  = (tid & 1) * 32;
#pragma unroll
        for (int jj = 0; jj < 8; jj++)
            *(float4*)&Qs[d_l][ih + jj * 4] =
                *(const float4*)(Qg + d_l * 1024 + i0 + ih + jj * 4);
    }

    float m[8], l[8], oacc[8][4];
    int xi[8], yi[8];
#pragma unroll
    for (int r = 0; r < 8; r++) {
        m[r] = -1e30f; l[r] = 0.f;
#pragma unroll
        for (int c = 0; c < 4; c++) oacc[r][c] = 0.f;
        int ig = i0 + ty * 8 + r;
        xi[r] = ig >> 5; yi[r] = ig & 31;
    }
    __syncthreads();

    for (int j0 = 0; j0 < 1024; j0 += 64) {
        {   // Ks[d][j], Vs[j][d] (transpose on store)
            int d_l = tid >> 1;
            int jh  = (tid & 1) * 32;
#pragma unroll
            for (int jj = 0; jj < 8; jj++) {
                float4 k4 = *(const float4*)(Kg + d_l * 1024 + j0 + jh + jj * 4);
                *(float4*)&Ks[d_l][jh + jj * 4] = k4;
                float4 v4 = *(const float4*)(Vg + d_l * 1024 + j0 + jh + jj * 4);
                int jb = jh + jj * 4;
                Vs[jb + 0][d_l] = v4.x;
                Vs[jb + 1][d_l] = v4.y;
                Vs[jb + 2][d_l] = v4.z;
                Vs[jb + 3][d_l] = v4.w;
            }
        }
        __syncthreads();

        // S = Q K^T tile
        float sacc[8][4];
#pragma unroll
        for (int r = 0; r < 8; r++)
#pragma unroll
            for (int c = 0; c < 4; c++) sacc[r][c] = 0.f;
        for (int d = 0; d < 64; d++) {
            float4 a0 = *(const float4*)&Qs[d][ty * 8];
            float4 a1 = *(const float4*)&Qs[d][ty * 8 + 4];
            float4 b0 = *(const float4*)&Ks[d][tx * 4];
            float a[8] = {a0.x, a0.y, a0.z, a0.w, a1.x, a1.y, a1.z, a1.w};
            float bb[4] = {b0.x, b0.y, b0.z, b0.w};
#pragma unroll
            for (int r = 0; r < 8; r++)
#pragma unroll
                for (int c = 0; c < 4; c++)
                    sacc[r][c] = fmaf(a[r], bb[c], sacc[r][c]);
        }

        // bias + online softmax (row groups = 16 consecutive lanes)
#pragma unroll
        for (int r = 0; r < 8; r++) {
            float rmax = -1e30f;
#pragma unroll
            for (int c = 0; c < 4; c++) {
                int jg = j0 + tx * 4 + c;
                int dx = xi[r] - (jg >> 5); dx = dx < 0 ? -dx : dx;
                int dy = yi[r] - (jg & 31); dy = dy < 0 ? -dy : dy;
                float sv = fmaf(sacc[r][c], 0.125f, semb[dx * 32 + dy]);
                sacc[r][c] = sv;
                rmax = fmaxf(rmax, sv);
            }
#pragma unroll
            for (int ofs = 1; ofs < 16; ofs <<= 1)
                rmax = fmaxf(rmax, __shfl_xor_sync(0xffffffffu, rmax, ofs));
            float mnew = fmaxf(m[r], rmax);
            float corr = __expf(m[r] - mnew);
            m[r] = mnew;
            float rsum = 0.f;
#pragma unroll
            for (int c = 0; c < 4; c++) {
                float p = __expf(sacc[r][c] - mnew);
                sacc[r][c] = p;
                rsum += p;
            }
#pragma unroll
            for (int ofs = 1; ofs < 16; ofs <<= 1)
                rsum += __shfl_xor_sync(0xffffffffu, rsum, ofs);
            l[r] = fmaf(l[r], corr, rsum);
#pragma unroll
            for (int c = 0; c < 4; c++) oacc[r][c] *= corr;
        }

        // P tile to smem, transposed: Ps[j][i]
#pragma unroll
        for (int c = 0; c < 4; c++) {
            float4 pv0, pv1;
            pv0.x = sacc[0][c]; pv0.y = sacc[1][c]; pv0.z = sacc[2][c]; pv0.w = sacc[3][c];
            pv1.x = sacc[4][c]; pv1.y = sacc[5][c]; pv1.z = sacc[6][c]; pv1.w = sacc[7][c];
            *(float4*)&Ps[tx * 4 + c][ty * 8]     = pv0;
            *(float4*)&Ps[tx * 4 + c][ty * 8 + 4] = pv1;
        }
        __syncthreads();

        // O += P @ V
        for (int j = 0; j < 64; j++) {
            float4 a0 = *(const float4*)&Ps[j][ty * 8];
            float4 a1 = *(const float4*)&Ps[j][ty * 8 + 4];
            float4 b0 = *(const float4*)&Vs[j][tx * 4];
            float a[8] = {a0.x, a0.y, a0.z, a0.w, a1.x, a1.y, a1.z, a1.w};
            float bb[4] = {b0.x, b0.y, b0.z, b0.w};
#pragma unroll
            for (int r = 0; r < 8; r++)
#pragma unroll
                for (int c = 0; c < 4; c++)
                    oacc[r][c] = fmaf(a[r], bb[c], oacc[r][c]);
        }
        __syncthreads();
    }

#pragma unroll
    for (int r = 0; r < 8; r++) {
        float inv = 1.0f / l[r];
        int ig = i0 + ty * 8 + r;
        float4 v;
        v.x = oacc[r][0] * inv;
        v.y = oacc[r][1] * inv;
        v.z = oacc[r][2] * inv;
        v.w = oacc[r][3] * inv;
        *(float4*)(g_o + (b * 1024 + ig) * 512 + h * 64 + tx * 4) = v;
    }
}

// ============================================================================
// Kernel 3: hardswish + output GEMM + BN.
// out[b, o, p] = bn( sum_c W2[o,c] * hswish(g_o[b, p, c]) + b_out[o] )
// ============================================================================
__global__ __launch_bounds__(128) void outproj_kernel(
    const float* __restrict__ W2, const float* __restrict__ b_out,
    const float* __restrict__ gam, const float* __restrict__ bet,
    const float* __restrict__ mu, const float* __restrict__ var,
    float* __restrict__ out)
{
    __shared__ float Ws[16][68];
    __shared__ float Xs[16][68];
    const int b  = blockIdx.z;
    const int o0 = blockIdx.y * 64;
    const int p0 = blockIdx.x * 64;
    const int tid = threadIdx.x;
    const int tx = tid & 15;
    const int ty = tid >> 4;
    const float* Ob = g_o + b * 1024 * 512;

    float acc[8][4];
#pragma unroll
    for (int r = 0; r < 8; r++)
#pragma unroll
        for (int c = 0; c < 4; c++) acc[r][c] = 0.f;

    for (int kk = 0; kk < 512; kk += 16) {
        {   // Ws[k][o]
            int o_l = tid >> 1;
            int k8  = (tid & 1) * 8;
#pragma unroll
            for (int jj = 0; jj < 2; jj++) {
                float4 w4 = *(const float4*)(W2 + (o0 + o_l) * 512 + kk + k8 + jj * 4);
                Ws[k8 + jj * 4 + 0][o_l] = w4.x;
                Ws[k8 + jj * 4 + 1][o_l] = w4.y;
                Ws[k8 + jj * 4 + 2][o_l] = w4.z;
                Ws[k8 + jj * 4 + 3][o_l] = w4.w;
            }
        }
        {   // Xs[k][p] = hardswish(Ob[p, k])
            int p_l = tid >> 1;
            int k8  = (tid & 1) * 8;
#pragma unroll
            for (int jj = 0; jj < 2; jj++) {
                float4 o4 = *(const float4*)(Ob + (p0 + p_l) * 512 + kk + k8 + jj * 4);
                Xs[k8 + jj * 4 + 0][p_l] = hswish(o4.x);
                Xs[k8 + jj * 4 + 1][p_l] = hswish(o4.y);
                Xs[k8 + jj * 4 + 2][p_l] = hswish(o4.z);
                Xs[k8 + jj * 4 + 3][p_l] = hswish(o4.w);
            }
        }
        __syncthreads();
#pragma unroll
        for (int k = 0; k < 16; k++) {
            float4 a0 = *(const float4*)&Ws[k][ty * 8];
            float4 a1 = *(const float4*)&Ws[k][ty * 8 + 4];
            float4 b0 = *(const float4*)&Xs[k][tx * 4];
            float a[8] = {a0.x, a0.y, a0.z, a0.w, a1.x, a1.y, a1.z, a1.w};
            float bb[4] = {b0.x, b0.y, b0.z, b0.w};
#pragma unroll
            for (int r = 0; r < 8; r++)
#pragma unroll
                for (int c = 0; c < 4; c++)
                    acc[r][c] = fmaf(a[r], bb[c], acc[r][c]);
        }
        __syncthreads();
    }
#pragma unroll
    for (int r = 0; r < 8; r++) {
        int o = o0 + ty * 8 + r;
        float s = gam[o] * rsqrtf(var[o] + EPS);
        float t = bet[o] - mu[o] * s;
        float4 v;
        v.x = (acc[r][0] + b_out[o]) * s + t;
        v.y = (acc[r][1] + b_out[o]) * s + t;
        v.z = (acc[r][2] + b_out[o]) * s + t;
        v.w = (acc[r][3] + b_out[o]) * s + t;
        *(float4*)(out + (b * 256 + o) * 1024 + p0 + tx * 4) = v;
    }
}

// ============================================================================
extern "C" void kernel_launch(void* const* d_in, const int* in_sizes, int n_in,
                              void* d_out, int out_size)
{
    const float* x    = (const float*)d_in[0];
    const float* wq   = (const float*)d_in[1];
    const float* gq   = (const float*)d_in[2];
    const float* bq   = (const float*)d_in[3];
    const float* mq   = (const float*)d_in[4];
    const float* vq   = (const float*)d_in[5];
    const float* wk   = (const float*)d_in[6];
    const float* gk   = (const float*)d_in[7];
    const float* bk   = (const float*)d_in[8];
    const float* mk   = (const float*)d_in[9];
    const float* vk   = (const float*)d_in[10];
    const float* wv   = (const float*)d_in[11];
    const float* gv   = (const float*)d_in[12];
    const float* bv   = (const float*)d_in[13];
    const float* mv   = (const float*)d_in[14];
    const float* vv   = (const float*)d_in[15];
    const float* emb  = (const float*)d_in[16];
    const float* w_o  = (const float*)d_in[17];
    const float* b_o  = (const float*)d_in[18];
    const float* go   = (const float*)d_in[19];
    const float* bo   = (const float*)d_in[20];
    const float* mo   = (const float*)d_in[21];
    const float* vo   = (const float*)d_in[22];
    // d_in[23] = pos_indices: recomputed on the fly in attn_kernel, unused.

    static bool attr_set = false;
    if (!attr_set) {
        cudaFuncSetAttribute(attn_kernel, cudaFuncAttributeMaxDynamicSharedMemorySize, 73728);
        attr_set = true;
    }

    dim3 blk(128);
    // Fused Q/K/V projections: z = which*16 + b
    proj_kernel<<<dim3(16, 8, 48), blk>>>(x, wq, wk, wv,
                                          gq, bq, mq, vq,
                                          gk, bk, mk, vk,
                                          gv, bv, mv, vv);
    attn_kernel<<<dim3(16, 128), blk, 73728>>>(emb);
    outproj_kernel<<<dim3(16, 4, 16), blk>>>(w_o, b_o, go, bo, mo, vo, (float*)d_out);
}

// round 7
// speedup vs baseline: 2.7446x; 2.7446x over previous
#include <cuda_runtime.h>
#include <cuda_fp16.h>
#include <mma.h>

using namespace nvcuda;

#define EPS 1e-5f

// ---- scratch (static device globals; no allocation at runtime) ----
static __device__ half g_q[16 * 512 * 1024];   // [b, h*64+d, i]  (ch-major)
static __device__ half g_k[16 * 512 * 1024];   // [b, h*64+d, j]  (ch-major)
static __device__ half g_v[16 * 512 * 1024];   // [b, h*64+d, j]  (ch-major)
static __device__ half g_o[16 * 1024 * 512];   // [b, i, h*64+d]  (pos-major)

__device__ __forceinline__ float hswish_f(float x) {
    return x * __saturatef((x + 3.0f) * (1.0f / 6.0f));
}

// ============================================================================
// Kernel 1: fused Q/K/V projection GEMM (fp16 wmma) + BN epilogue, half out.
// out[b,o,p] = bn(sum_c W[o,c] * X[b,c,p]).  Tile 128o x 128p, 256 thr.
// gridDim.z = which*16 + b.
// ============================================================================
__global__ __launch_bounds__(256) void proj_kernel(
    const float* __restrict__ X,
    const float* __restrict__ Wq, const float* __restrict__ Wk, const float* __restrict__ Wv,
    const float* __restrict__ gq, const float* __restrict__ bq,
    const float* __restrict__ mq, const float* __restrict__ vq,
    const float* __restrict__ gk, const float* __restrict__ bk,
    const float* __restrict__ mk, const float* __restrict__ vk,
    const float* __restrict__ gv, const float* __restrict__ bv,
    const float* __restrict__ mv, const float* __restrict__ vv)
{
    __shared__ half Ws[128][40];    // A: W[o][c-chunk], row_major
    __shared__ half Xs[32][136];    // B: X[c-chunk][p], row_major
    __shared__ float so[128], to[128];
    __shared__ float Es[8][384];    // per-warp 16x24 epilogue scratch

    const int which = blockIdx.z >> 4;
    const int b     = blockIdx.z & 15;
    const float* W   = (which == 0) ? Wq : (which == 1) ? Wk : Wv;
    const float* gam = (which == 0) ? gq : (which == 1) ? gk : gv;
    const float* bet = (which == 0) ? bq : (which == 1) ? bk : bv;
    const float* mu  = (which == 0) ? mq : (which == 1) ? mk : mv;
    const float* var = (which == 0) ? vq : (which == 1) ? vk : vv;
    half* outbuf     = (which == 0) ? g_q : (which == 1) ? g_k : g_v;

    const int o0 = blockIdx.y * 128;
    const int p0 = blockIdx.x * 128;
    const int tid  = threadIdx.x;
    const int warp = tid >> 5;
    const int lane = tid & 31;

    if (tid < 128) {
        int o = o0 + tid;
        float s = gam[o] * rsqrtf(var[o] + EPS);
        so[tid] = s;
        to[tid] = bet[o] - mu[o] * s;
    }

    const int wo = (warp >> 1) * 32;   // 4 warps over o
    const int wp = (warp & 1) * 64;    // 2 warps over p

    wmma::fragment<wmma::accumulator, 16, 16, 16, float> acc[2][4];
#pragma unroll
    for (int i = 0; i < 2; i++)
#pragma unroll
        for (int j = 0; j < 4; j++) wmma::fill_fragment(acc[i][j], 0.0f);

    const float* Xb = X + (size_t)b * 256 * 1024;

    for (int kk = 0; kk < 256; kk += 32) {
        {   // Ws[o][kc] <- W fp32->half
            int o = tid >> 1, kc0 = (tid & 1) * 16;
            const float4* src = (const float4*)(W + (size_t)(o0 + o) * 256 + kk + kc0);
            half2* dst = (half2*)(&Ws[o][kc0]);
#pragma unroll
            for (int u = 0; u < 4; u++) {
                float4 f = src[u];
                dst[u * 2 + 0] = __floats2half2_rn(f.x, f.y);
                dst[u * 2 + 1] = __floats2half2_rn(f.z, f.w);
            }
        }
        {   // Xs[kc][p] <- X fp32->half
            int kc = tid >> 3, pb = (tid & 7) * 16;
            const float4* src = (const float4*)(Xb + (size_t)(kk + kc) * 1024 + p0 + pb);
            half2* dst = (half2*)(&Xs[kc][pb]);
#pragma unroll
            for (int u = 0; u < 4; u++) {
                float4 f = src[u];
                dst[u * 2 + 0] = __floats2half2_rn(f.x, f.y);
                dst[u * 2 + 1] = __floats2half2_rn(f.z, f.w);
            }
        }
        __syncthreads();
#pragma unroll
        for (int ks = 0; ks < 32; ks += 16) {
            wmma::fragment<wmma::matrix_a, 16, 16, 16, half, wmma::row_major> a[2];
            wmma::load_matrix_sync(a[0], &Ws[wo][ks], 40);
            wmma::load_matrix_sync(a[1], &Ws[wo + 16][ks], 40);
#pragma unroll
            for (int nf = 0; nf < 4; nf++) {
                wmma::fragment<wmma::matrix_b, 16, 16, 16, half, wmma::row_major> bf;
                wmma::load_matrix_sync(bf, &Xs[ks][wp + nf * 16], 136);
                wmma::mma_sync(acc[0][nf], a[0], bf, acc[0][nf]);
                wmma::mma_sync(acc[1][nf], a[1], bf, acc[1][nf]);
            }
        }
        __syncthreads();
    }

    // Epilogue: BN, convert half, store [o][p]
    float* es = &Es[warp][0];
#pragma unroll
    for (int mf = 0; mf < 2; mf++)
#pragma unroll
        for (int nf = 0; nf < 4; nf++) {
            wmma::store_matrix_sync(es, acc[mf][nf], 24, wmma::mem_row_major);
            __syncwarp();
            int r = lane >> 1, cb = (lane & 1) * 8;
            int o_l = wo + mf * 16 + r;
            float s = so[o_l], t = to[o_l];
            union { uint4 u; half h[8]; } hb;
#pragma unroll
            for (int c = 0; c < 8; c++)
                hb.h[c] = __float2half(es[r * 24 + cb + c] * s + t);
            int o = o0 + o_l;
            int p = p0 + wp + nf * 16 + cb;
            *(uint4*)(outbuf + ((size_t)(b * 512 + o) * 1024 + p)) = hb.u;
            __syncwarp();
        }
}

// ============================================================================
// Kernel 2: attention per (b,h), 128 i-rows per block, fp16 wmma, streaming
// softmax WITHOUT max subtraction (|S| <~ 6, exp-safe in fp32).
// S = 0.125*QK^T + 8*emb[idx], P = exp(S), O = (P@V) / rowsum(P).
// ============================================================================
__global__ __launch_bounds__(256) void attn_kernel(const float* __restrict__ emb)
{
    extern __shared__ char smc[];
    float* Ss   = (float*)(smc);                 // 8 warps * 16*72 f = 36864 B
    float* semb = (float*)(smc + 36864);         // 1024 f            =  4096 B
    half*  Qs   = (half*) (smc + 40960);         // 64*136 h          = 17408 B
    half*  Ks   = (half*) (smc + 58368);         // 64*72 h           =  9216 B
    half*  Vs   = (half*) (smc + 67584);         // 64*72 h           =  9216 B
    half*  Ps   = (half*) (smc + 76800);         // 128*72 h          = 18432 B
    // total 95232 B

    const int bh = blockIdx.y;
    const int b = bh >> 3, h = bh & 7;
    const int i0 = blockIdx.x * 128;
    const int tid  = threadIdx.x;
    const int warp = tid >> 5;
    const int lane = tid & 31;

    const half* Qg = g_q + (size_t)(b * 512 + h * 64) * 1024;
    const half* Kg = g_k + (size_t)(b * 512 + h * 64) * 1024;
    const half* Vg = g_v + (size_t)(b * 512 + h * 64) * 1024;

    for (int i = tid; i < 1024; i += 256)
        semb[i] = emb[i * 8 + h] * 8.0f;

    {   // Qs[d][i] direct copy (col_major A for wmma)
        int d = tid >> 2, cb = (tid & 3) * 32;
        const uint4* src = (const uint4*)(Qg + (size_t)d * 1024 + i0 + cb);
        uint4* dst = (uint4*)(Qs + d * 136 + cb);
#pragma unroll
        for (int u = 0; u < 4; u++) dst[u] = src[u];
    }

    const int iw = warp * 16;
    const int r    = lane >> 1;          // row within warp tile
    const int jcol = (lane & 1) * 32;    // 32-wide column half
    const int irow = i0 + iw + r;
    const int xi = irow >> 5, yi = irow & 31;

    wmma::fragment<wmma::accumulator, 16, 16, 16, float> o_acc[4];
#pragma unroll
    for (int nf = 0; nf < 4; nf++) wmma::fill_fragment(o_acc[nf], 0.0f);
    float l_acc = 0.0f;

    float* ssw = Ss + warp * 16 * 72;

    for (int j0 = 0; j0 < 1024; j0 += 64) {
        __syncthreads();   // protect Ks/Vs from previous tile's MMA reads
        {   // Ks[d][j] direct copy
            int d = tid & 63, cb = (tid >> 6) * 16;
            const uint4* src = (const uint4*)(Kg + (size_t)d * 1024 + j0 + cb);
            uint4* dst = (uint4*)(Ks + d * 72 + cb);
            dst[0] = src[0];
            dst[1] = src[1];
        }
        {   // Vs[j][d] transpose on store
            int d = tid & 63, jb = (tid >> 6) * 16;
            const half* src = Vg + (size_t)d * 1024 + j0 + jb;
            half* dst = Vs + d;
#pragma unroll
            for (int jj = 0; jj < 16; jj += 2) {
                half2 v2 = *(const half2*)(src + jj);
                dst[(jb + jj) * 72]     = __low2half(v2);
                dst[(jb + jj + 1) * 72] = __high2half(v2);
            }
        }
        __syncthreads();

        // S = Q^T-stored @ K  (A col_major from Qs[d][i], B row_major Ks[d][j])
        wmma::fragment<wmma::accumulator, 16, 16, 16, float> s_frag[4];
#pragma unroll
        for (int jf = 0; jf < 4; jf++) wmma::fill_fragment(s_frag[jf], 0.0f);
#pragma unroll
        for (int dk = 0; dk < 4; dk++) {
            wmma::fragment<wmma::matrix_a, 16, 16, 16, half, wmma::col_major> aq;
            wmma::load_matrix_sync(aq, Qs + dk * 16 * 136 + iw, 136);
#pragma unroll
            for (int jf = 0; jf < 4; jf++) {
                wmma::fragment<wmma::matrix_b, 16, 16, 16, half, wmma::row_major> bk;
                wmma::load_matrix_sync(bk, Ks + dk * 16 * 72 + jf * 16, 72);
                wmma::mma_sync(s_frag[jf], aq, bk, s_frag[jf]);
            }
        }
#pragma unroll
        for (int jf = 0; jf < 4; jf++)
            wmma::store_matrix_sync(ssw + jf * 16, s_frag[jf], 72, wmma::mem_row_major);
        __syncwarp();

        // softmax (no max-sub): p = exp(0.125*s + bias), accumulate row sums
        {
            const float* srow = ssw + r * 72 + jcol;
            half* prow = Ps + (iw + r) * 72 + jcol;
            float lsum = 0.0f;
#pragma unroll
            for (int c = 0; c < 32; c += 2) {
                int j  = j0 + jcol + c;
                int xj0 = j >> 5,       yj0 = j & 31;
                int xj1 = (j + 1) >> 5, yj1 = (j + 1) & 31;
                int d0 = abs(xi - xj0) * 32 + abs(yi - yj0);
                int d1 = abs(xi - xj1) * 32 + abs(yi - yj1);
                float e0 = __expf(fmaf(srow[c],     0.125f, semb[d0]));
                float e1 = __expf(fmaf(srow[c + 1], 0.125f, semb[d1]));
                lsum += e0 + e1;
                *(half2*)(prow + c) = __floats2half2_rn(e0, e1);
            }
            lsum += __shfl_xor_sync(0xffffffffu, lsum, 1);
            l_acc += lsum;
        }
        __syncwarp();

        // O += P @ V   (A row_major Ps[i][j], B row_major Vs[j][d])
#pragma unroll
        for (int jk = 0; jk < 4; jk++) {
            wmma::fragment<wmma::matrix_a, 16, 16, 16, half, wmma::row_major> ap;
            wmma::load_matrix_sync(ap, Ps + iw * 72 + jk * 16, 72);
#pragma unroll
            for (int nf = 0; nf < 4; nf++) {
                wmma::fragment<wmma::matrix_b, 16, 16, 16, half, wmma::row_major> bv;
                wmma::load_matrix_sync(bv, Vs + jk * 16 * 72 + nf * 16, 72);
                wmma::mma_sync(o_acc[nf], ap, bv, o_acc[nf]);
            }
        }
    }

    // Epilogue: normalize by row sum, write g_o[b][i][h*64+d] as half
#pragma unroll
    for (int nf = 0; nf < 4; nf++)
        wmma::store_matrix_sync(ssw + nf * 16, o_acc[nf], 72, wmma::mem_row_major);
    __syncwarp();
    {
        float inv = 1.0f / l_acc;   // lane's pair-summed row total (row r)
        const float* orow = ssw + r * 72 + jcol;   // jcol doubles as d-offset (0/32)
        half* dst = g_o + ((size_t)(b * 1024 + i0 + iw + r) * 512 + h * 64 + jcol);
#pragma unroll
        for (int c = 0; c < 32; c += 2)
            *(half2*)(dst + c) = __floats2half2_rn(orow[c] * inv, orow[c + 1] * inv);
    }
}

// ============================================================================
// Kernel 3: hardswish + output GEMM (fp16 wmma, computes out^T) + bias + BN.
// out[b,o,p] = bn( sum_c W2[o,c]*hswish(g_o[b,p,c]) + b_out[o] ).
// A = hswish(g_o)[p][c] row_major, B = W2[o][c] as col_major -> acc (p,o).
// ============================================================================
__global__ __launch_bounds__(256) void outproj_kernel(
    const float* __restrict__ W2, const float* __restrict__ b_out,
    const float* __restrict__ gam, const float* __restrict__ bet,
    const float* __restrict__ mu, const float* __restrict__ var,
    float* __restrict__ out)
{
    __shared__ half As[128][40];   // hswish(g_o)[p][c-chunk]
    __shared__ half Bs[128][40];   // W2[o][c-chunk]
    __shared__ float so[128], to[128], bo_s[128];
    __shared__ float Es[8][384];

    const int b  = blockIdx.z;
    const int o0 = blockIdx.y * 128;
    const int p0 = blockIdx.x * 128;
    const int tid  = threadIdx.x;
    const int warp = tid >> 5;
    const int lane = tid & 31;
    const half* Ob = g_o + (size_t)b * 1024 * 512;

    if (tid < 128) {
        int o = o0 + tid;
        float s = gam[o] * rsqrtf(var[o] + EPS);
        so[tid] = s;
        to[tid] = bet[o] - mu[o] * s;
        bo_s[tid] = b_out[o];
    }

    const int wp = (warp >> 1) * 32;   // 4 warps over p (m)
    const int wo = (warp & 1) * 64;    // 2 warps over o (n)

    wmma::fragment<wmma::accumulator, 16, 16, 16, float> acc[2][4];
#pragma unroll
    for (int i = 0; i < 2; i++)
#pragma unroll
        for (int j = 0; j < 4; j++) wmma::fill_fragment(acc[i][j], 0.0f);

    for (int kk = 0; kk < 512; kk += 32) {
        {   // As[p][kc] <- hswish(g_o half)
            int p = tid >> 1, kc0 = (tid & 1) * 16;
            const uint4* src = (const uint4*)(Ob + (size_t)(p0 + p) * 512 + kk + kc0);
            uint4 raw[2] = {src[0], src[1]};
            const half* hr = (const half*)raw;
            half2* dst = (half2*)(&As[p][kc0]);
#pragma unroll
            for (int u = 0; u < 8; u++) {
                float x0 = __half2float(hr[u * 2]);
                float x1 = __half2float(hr[u * 2 + 1]);
                dst[u] = __floats2half2_rn(hswish_f(x0), hswish_f(x1));
            }
        }
        {   // Bs[o][kc] <- W2 fp32->half
            int o = tid >> 1, kc0 = (tid & 1) * 16;
            const float4* src = (const float4*)(W2 + (size_t)(o0 + o) * 512 + kk + kc0);
            half2* dst = (half2*)(&Bs[o][kc0]);
#pragma unroll
            for (int u = 0; u < 4; u++) {
                float4 f = src[u];
                dst[u * 2 + 0] = __floats2half2_rn(f.x, f.y);
                dst[u * 2 + 1] = __floats2half2_rn(f.z, f.w);
            }
        }
        __syncthreads();
#pragma unroll
        for (int ks = 0; ks < 32; ks += 16) {
            wmma::fragment<wmma::matrix_a, 16, 16, 16, half, wmma::row_major> a[2];
            wmma::load_matrix_sync(a[0], &As[wp][ks], 40);
            wmma::load_matrix_sync(a[1], &As[wp + 16][ks], 40);
#pragma unroll
            for (int nf = 0; nf < 4; nf++) {
                wmma::fragment<wmma::matrix_b, 16, 16, 16, half, wmma::col_major> bf;
                wmma::load_matrix_sync(bf, &Bs[wo + nf * 16][ks], 40);
                wmma::mma_sync(acc[0][nf], a[0], bf, acc[0][nf]);
                wmma::mma_sync(acc[1][nf], a[1], bf, acc[1][nf]);
            }
        }
        __syncthreads();
    }

    // Epilogue: acc (m=p, n=o); col-major store -> es[o][p], BN per o, fp32 out
    float* es = &Es[warp][0];
#pragma unroll
    for (int mf = 0; mf < 2; mf++)
#pragma unroll
        for (int nf = 0; nf < 4; nf++) {
            wmma::store_matrix_sync(es, acc[mf][nf], 24, wmma::mem_col_major);
            __syncwarp();
            int r = lane >> 1, cb = (lane & 1) * 8;   // r -> o row, cb -> p cols
            int o_l = wo + nf * 16 + r;
            int p_l = wp + mf * 16 + cb;
            float s = so[o_l], t = to[o_l], bb = bo_s[o_l];
            float* dst = out + (size_t)(b * 256 + o0 + o_l) * 1024 + p0 + p_l;
            float4 v0, v1;
            const float* er = es + r * 24 + cb;
            v0.x = (er[0] + bb) * s + t;  v0.y = (er[1] + bb) * s + t;
            v0.z = (er[2] + bb) * s + t;  v0.w = (er[3] + bb) * s + t;
            v1.x = (er[4] + bb) * s + t;  v1.y = (er[5] + bb) * s + t;
            v1.z = (er[6] + bb) * s + t;  v1.w = (er[7] + bb) * s + t;
            *(float4*)dst = v0;
            *(float4*)(dst + 4) = v1;
            __syncwarp();
        }
}

// ============================================================================
extern "C" void kernel_launch(void* const* d_in, const int* in_sizes, int n_in,
                              void* d_out, int out_size)
{
    const float* x    = (const float*)d_in[0];
    const float* wq   = (const float*)d_in[1];
    const float* gq   = (const float*)d_in[2];
    const float* bq   = (const float*)d_in[3];
    const float* mq   = (const float*)d_in[4];
    const float* vq   = (const float*)d_in[5];
    const float* wk   = (const float*)d_in[6];
    const float* gk   = (const float*)d_in[7];
    const float* bk   = (const float*)d_in[8];
    const float* mk   = (const float*)d_in[9];
    const float* vk   = (const float*)d_in[10];
    const float* wv   = (const float*)d_in[11];
    const float* gv   = (const float*)d_in[12];
    const float* bv   = (const float*)d_in[13];
    const float* mv   = (const float*)d_in[14];
    const float* vv   = (const float*)d_in[15];
    const float* emb  = (const float*)d_in[16];
    const float* w_o  = (const float*)d_in[17];
    const float* b_o  = (const float*)d_in[18];
    const float* go   = (const float*)d_in[19];
    const float* bo   = (const float*)d_in[20];
    const float* mo   = (const float*)d_in[21];
    const float* vo   = (const float*)d_in[22];
    // d_in[23] = pos_indices: recomputed on the fly in attn_kernel, unused.

    static bool attr_set = false;
    if (!attr_set) {
        cudaFuncSetAttribute(attn_kernel, cudaFuncAttributeMaxDynamicSharedMemorySize, 95232);
        attr_set = true;
    }

    proj_kernel<<<dim3(8, 4, 48), 256>>>(x, wq, wk, wv,
                                         gq, bq, mq, vq,
                                         gk, bk, mk, vk,
                                         gv, bv, mv, vv);
    attn_kernel<<<dim3(8, 128), 256, 95232>>>(emb);
    outproj_kernel<<<dim3(8, 2, 16), 256>>>(w_o, b_o, go, bo, mo, vo, (float*)d_out);
}

// round 11
// speedup vs baseline: 4.3829x; 1.5969x over previous
#include <cuda_runtime.h>
#include <cuda_fp16.h>
#include <mma.h>
#include <cstdint>

using namespace nvcuda;

#define EPS 1e-5f

// ---- scratch (static device globals; no allocation at runtime) ----
static __device__ half g_q[16 * 512 * 1024];   // [b, h*64+d, i]  (ch-major)
static __device__ half g_k[16 * 512 * 1024];   // [b, h*64+d, j]  (ch-major)
static __device__ half g_v[16 * 512 * 1024];   // [b, h*64+d, j]  (ch-major)
static __device__ half g_o[16 * 1024 * 512];   // [b, i, h*64+d]  (pos-major)

__device__ __forceinline__ float hswish_f(float x) {
    return x * __saturatef((x + 3.0f) * (1.0f / 6.0f));
}

__device__ __forceinline__ uint32_t packh2(float a, float b) {
    __half2 h = __floats2half2_rn(a, b);
    return *reinterpret_cast<uint32_t*>(&h);
}

// mma.sync m16n8k16 row.col f32.f16.f16.f32, accumulate in place
__device__ __forceinline__ void mma16816(float* d, const uint32_t* a, uint32_t b0, uint32_t b1) {
    asm volatile(
        "mma.sync.aligned.m16n8k16.row.col.f32.f16.f16.f32 "
        "{%0,%1,%2,%3}, {%4,%5,%6,%7}, {%8,%9}, {%0,%1,%2,%3};\n"
        : "+f"(d[0]), "+f"(d[1]), "+f"(d[2]), "+f"(d[3])
        : "r"(a[0]), "r"(a[1]), "r"(a[2]), "r"(a[3]), "r"(b0), "r"(b1));
}

// ============================================================================
// Kernel 1: fused Q/K/V projection GEMM (fp16 wmma, 2-stage pipeline) + BN.
// out[b,o,p] = bn(sum_c W[o,c] * X[b,c,p]).  Tile 128o x 128p, 256 thr.
// Dynamic smem: 2 stages x (Ws 128x40 half | Xs 32x136 half) = 37888 B.
// ============================================================================
__global__ __launch_bounds__(256) void proj_kernel(
    const float* __restrict__ X,
    const float* __restrict__ Wq, const float* __restrict__ Wk, const float* __restrict__ Wv,
    const float* __restrict__ gq, const float* __restrict__ bq,
    const float* __restrict__ mq, const float* __restrict__ vq,
    const float* __restrict__ gk, const float* __restrict__ bk,
    const float* __restrict__ mk, const float* __restrict__ vk,
    const float* __restrict__ gv, const float* __restrict__ bv,
    const float* __restrict__ mv, const float* __restrict__ vv)
{
    extern __shared__ char ps[];
    __shared__ float so[128], to[128];
    __shared__ float Es[8][384];

    const int which = blockIdx.z >> 4;
    const int b     = blockIdx.z & 15;
    const float* W   = (which == 0) ? Wq : (which == 1) ? Wk : Wv;
    const float* gam = (which == 0) ? gq : (which == 1) ? gk : gv;
    const float* bet = (which == 0) ? bq : (which == 1) ? bk : bv;
    const float* mu  = (which == 0) ? mq : (which == 1) ? mk : mv;
    const float* var = (which == 0) ? vq : (which == 1) ? vk : vv;
    half* outbuf     = (which == 0) ? g_q : (which == 1) ? g_k : g_v;

    const int o0 = blockIdx.y * 128;
    const int p0 = blockIdx.x * 128;
    const int tid  = threadIdx.x;
    const int warp = tid >> 5;
    const int lane = tid & 31;

    if (tid < 128) {
        int o = o0 + tid;
        float s = gam[o] * rsqrtf(var[o] + EPS);
        so[tid] = s;
        to[tid] = bet[o] - mu[o] * s;
    }

    const int wo = (warp >> 1) * 32;
    const int wp = (warp & 1) * 64;

    wmma::fragment<wmma::accumulator, 16, 16, 16, float> acc[2][4];
#pragma unroll
    for (int i = 0; i < 2; i++)
#pragma unroll
        for (int j = 0; j < 4; j++) wmma::fill_fragment(acc[i][j], 0.0f);

    const float* Xb = X + (size_t)b * 256 * 1024;

    const int wrow = tid >> 1, wkc = (tid & 1) * 16;      // W staging
    const int xkc  = tid >> 3, xpb = (tid & 7) * 16;      // X staging

    float4 wreg[4], xreg[4];
    // prologue load chunk 0
    {
        const float4* ws = (const float4*)(W + (size_t)(o0 + wrow) * 256 + 0 + wkc);
        const float4* xs = (const float4*)(Xb + (size_t)(0 + xkc) * 1024 + p0 + xpb);
#pragma unroll
        for (int u = 0; u < 4; u++) { wreg[u] = ws[u]; xreg[u] = xs[u]; }
    }
    {
        half2* wd = (half2*)(ps + 0 * 18944 + (wrow * 40 + wkc) * 2);
        half2* xd = (half2*)(ps + 0 * 18944 + 10240 + (xkc * 136 + xpb) * 2);
#pragma unroll
        for (int u = 0; u < 4; u++) {
            wd[u * 2 + 0] = __floats2half2_rn(wreg[u].x, wreg[u].y);
            wd[u * 2 + 1] = __floats2half2_rn(wreg[u].z, wreg[u].w);
            xd[u * 2 + 0] = __floats2half2_rn(xreg[u].x, xreg[u].y);
            xd[u * 2 + 1] = __floats2half2_rn(xreg[u].z, xreg[u].w);
        }
    }
    __syncthreads();

    for (int kk = 0, s = 0; kk < 256; kk += 32, s ^= 1) {
        const bool more = (kk + 32 < 256);
        if (more) {
            const float4* ws = (const float4*)(W + (size_t)(o0 + wrow) * 256 + kk + 32 + wkc);
            const float4* xs = (const float4*)(Xb + (size_t)(kk + 32 + xkc) * 1024 + p0 + xpb);
#pragma unroll
            for (int u = 0; u < 4; u++) { wreg[u] = ws[u]; xreg[u] = xs[u]; }
        }
        half* Wst = (half*)(ps + s * 18944);
        half* Xst = (half*)(ps + s * 18944 + 10240);
#pragma unroll
        for (int ks = 0; ks < 32; ks += 16) {
            wmma::fragment<wmma::matrix_a, 16, 16, 16, half, wmma::row_major> a[2];
            wmma::load_matrix_sync(a[0], Wst + wo * 40 + ks, 40);
            wmma::load_matrix_sync(a[1], Wst + (wo + 16) * 40 + ks, 40);
#pragma unroll
            for (int nf = 0; nf < 4; nf++) {
                wmma::fragment<wmma::matrix_b, 16, 16, 16, half, wmma::row_major> bf;
                wmma::load_matrix_sync(bf, Xst + ks * 136 + wp + nf * 16, 136);
                wmma::mma_sync(acc[0][nf], a[0], bf, acc[0][nf]);
                wmma::mma_sync(acc[1][nf], a[1], bf, acc[1][nf]);
            }
        }
        if (more) {
            half2* wd = (half2*)(ps + (s ^ 1) * 18944 + (wrow * 40 + wkc) * 2);
            half2* xd = (half2*)(ps + (s ^ 1) * 18944 + 10240 + (xkc * 136 + xpb) * 2);
#pragma unroll
            for (int u = 0; u < 4; u++) {
                wd[u * 2 + 0] = __floats2half2_rn(wreg[u].x, wreg[u].y);
                wd[u * 2 + 1] = __floats2half2_rn(wreg[u].z, wreg[u].w);
                xd[u * 2 + 0] = __floats2half2_rn(xreg[u].x, xreg[u].y);
                xd[u * 2 + 1] = __floats2half2_rn(xreg[u].z, xreg[u].w);
            }
        }
        __syncthreads();
    }

    // Epilogue: BN, convert half, store [o][p]
    float* es = &Es[warp][0];
#pragma unroll
    for (int mf = 0; mf < 2; mf++)
#pragma unroll
        for (int nf = 0; nf < 4; nf++) {
            wmma::store_matrix_sync(es, acc[mf][nf], 24, wmma::mem_row_major);
            __syncwarp();
            int r = lane >> 1, cb = (lane & 1) * 8;
            int o_l = wo + mf * 16 + r;
            float s = so[o_l], t = to[o_l];
            union { uint4 u; half h[8]; } hb;
#pragma unroll
            for (int c = 0; c < 8; c++)
                hb.h[c] = __float2half(es[r * 24 + cb + c] * s + t);
            int o = o0 + o_l;
            int p = p0 + wp + nf * 16 + cb;
            *(uint4*)(outbuf + ((size_t)(b * 512 + o) * 1024 + p)) = hb.u;
            __syncwarp();
        }
}

// ============================================================================
// Kernel 2: attention, mma.sync m16n8k16, in-register streaming softmax
// (no max-sub; |S|<~6), double-buffered K/V with register prefetch.
// Per block: 128 i-rows, 8 warps (16 rows each), j-tiles of 64, d=64.
// smem: Qs[128][72] | Ks[2][64][72] (j,d) | Vs[2][64][72] (d,j) | semb[1024]
// ============================================================================
__global__ __launch_bounds__(256) void attn_kernel(const float* __restrict__ emb)
{
    extern __shared__ char smc[];
    half*  Qs   = (half*)(smc);              // 128*72*2      = 18432 B
    half*  Ks   = (half*)(smc + 18432);      // 2*64*72*2     = 18432 B
    half*  Vs   = (half*)(smc + 36864);      // 2*64*72*2     = 18432 B
    float* semb = (float*)(smc + 55296);     // 1024*4        =  4096 B
    // total 59392 B

    const int bh = blockIdx.y;
    const int b = bh >> 3, h = bh & 7;
    const int i0 = blockIdx.x * 128;
    const int tid  = threadIdx.x;
    const int warp = tid >> 5;
    const int lane = tid & 31;
    const int g    = lane >> 2;      // row in fragment (0..7)
    const int tig  = lane & 3;       // thread-in-group

    const half* Qg = g_q + (size_t)(b * 512 + h * 64) * 1024;
    const half* Kg = g_k + (size_t)(b * 512 + h * 64) * 1024;
    const half* Vg = g_v + (size_t)(b * 512 + h * 64) * 1024;

    for (int i = tid; i < 1024; i += 256)
        semb[i] = emb[i * 8 + h] * 8.0f;

    // Q transpose into Qs[i][d]
    {
        int d = tid & 63, ib = (tid >> 6) * 32;
        const half* src = Qg + (size_t)d * 1024 + i0 + ib;
        uint4 q[4];
#pragma unroll
        for (int u = 0; u < 4; u++) q[u] = *(const uint4*)(src + u * 8);
        const half* hq = (const half*)q;
#pragma unroll
        for (int ii = 0; ii < 32; ii++)
            Qs[(ib + ii) * 72 + d] = hq[ii];
    }

    // tile 0: K (transpose -> [j][d]) and V (direct [d][j]) into stage 0
    const int dK = tid & 63, jb = (tid >> 6) * 16;
    {
        const half* ksrc = Kg + (size_t)dK * 1024 + jb;
        uint4 k0 = *(const uint4*)(ksrc), k1 = *(const uint4*)(ksrc + 8);
        const half* kh = (const half*)&k0;
#pragma unroll
        for (int jj = 0; jj < 8; jj++) Ks[(jb + jj) * 72 + dK] = kh[jj];
        kh = (const half*)&k1;
#pragma unroll
        for (int jj = 0; jj < 8; jj++) Ks[(jb + 8 + jj) * 72 + dK] = kh[jj];
        const half* vsrc = Vg + (size_t)dK * 1024 + jb;
        *(uint4*)&Vs[dK * 72 + jb]     = *(const uint4*)(vsrc);
        *(uint4*)&Vs[dK * 72 + jb + 8] = *(const uint4*)(vsrc + 8);
    }
    __syncthreads();

    // Q A-fragments, held in registers for the whole kernel
    const int iw = warp * 16;
    uint32_t qa[4][4];
#pragma unroll
    for (int dk = 0; dk < 4; dk++) {
        int dbase = dk * 16 + 2 * tig;
        qa[dk][0] = *(const uint32_t*)&Qs[(iw + g) * 72 + dbase];
        qa[dk][1] = *(const uint32_t*)&Qs[(iw + g + 8) * 72 + dbase];
        qa[dk][2] = *(const uint32_t*)&Qs[(iw + g) * 72 + dbase + 8];
        qa[dk][3] = *(const uint32_t*)&Qs[(iw + g + 8) * 72 + dbase + 8];
    }

    const int ig  = i0 + iw + g;
    const int ig8 = ig + 8;
    const int xi0 = ig >> 5,  yi0 = ig & 31;
    const int xi8 = ig8 >> 5, yi8 = ig8 & 31;

    float oacc[8][4];
#pragma unroll
    for (int nf = 0; nf < 8; nf++)
#pragma unroll
        for (int c = 0; c < 4; c++) oacc[nf][c] = 0.0f;
    float l0 = 0.0f, l1 = 0.0f;

    for (int t = 0; t < 16; t++) {
        // prefetch next tile into registers
        uint4 kpre0, kpre1, vpre0, vpre1;
        if (t < 15) {
            int j0n = (t + 1) * 64;
            const half* ksrc = Kg + (size_t)dK * 1024 + j0n + jb;
            kpre0 = *(const uint4*)(ksrc);
            kpre1 = *(const uint4*)(ksrc + 8);
            const half* vsrc = Vg + (size_t)dK * 1024 + j0n + jb;
            vpre0 = *(const uint4*)(vsrc);
            vpre1 = *(const uint4*)(vsrc + 8);
        }

        const half* Kc = Ks + (t & 1) * 4608;
        const half* Vc = Vs + (t & 1) * 4608;

        // S = Q K^T : 8 n-frags x 4 k-steps
        float sacc[8][4];
#pragma unroll
        for (int nf = 0; nf < 8; nf++)
#pragma unroll
            for (int c = 0; c < 4; c++) sacc[nf][c] = 0.0f;
#pragma unroll
        for (int dk = 0; dk < 4; dk++) {
#pragma unroll
            for (int nf = 0; nf < 8; nf++) {
                const half* kb = Kc + (nf * 8 + g) * 72 + dk * 16 + 2 * tig;
                uint32_t b0 = *(const uint32_t*)(kb);
                uint32_t b1 = *(const uint32_t*)(kb + 8);
                mma16816(sacc[nf], qa[dk], b0, b1);
            }
        }

        // bias + exp, in registers
        const int jt = t * 64 + 2 * tig;
#pragma unroll
        for (int nf = 0; nf < 8; nf++) {
            int j0e = jt + nf * 8;
            int xj0 = j0e >> 5,       yj0 = j0e & 31;
            int xj1 = (j0e + 1) >> 5, yj1 = (j0e + 1) & 31;
            float bi00 = semb[abs(xi0 - xj0) * 32 + abs(yi0 - yj0)];
            float bi01 = semb[abs(xi0 - xj1) * 32 + abs(yi0 - yj1)];
            float bi10 = semb[abs(xi8 - xj0) * 32 + abs(yi8 - yj0)];
            float bi11 = semb[abs(xi8 - xj1) * 32 + abs(yi8 - yj1)];
            float e0 = __expf(fmaf(sacc[nf][0], 0.125f, bi00));
            float e1 = __expf(fmaf(sacc[nf][1], 0.125f, bi01));
            float e2 = __expf(fmaf(sacc[nf][2], 0.125f, bi10));
            float e3 = __expf(fmaf(sacc[nf][3], 0.125f, bi11));
            l0 += e0 + e1;
            l1 += e2 + e3;
            sacc[nf][0] = e0; sacc[nf][1] = e1;
            sacc[nf][2] = e2; sacc[nf][3] = e3;
        }

        // O += P V : P accumulator fragments re-used directly as A operands
#pragma unroll
        for (int kf = 0; kf < 4; kf++) {
            uint32_t pa[4];
            pa[0] = packh2(sacc[2 * kf][0],     sacc[2 * kf][1]);
            pa[1] = packh2(sacc[2 * kf][2],     sacc[2 * kf][3]);
            pa[2] = packh2(sacc[2 * kf + 1][0], sacc[2 * kf + 1][1]);
            pa[3] = packh2(sacc[2 * kf + 1][2], sacc[2 * kf + 1][3]);
#pragma unroll
            for (int nf = 0; nf < 8; nf++) {
                const half* vb = Vc + (nf * 8 + g) * 72 + kf * 16 + 2 * tig;
                uint32_t b0 = *(const uint32_t*)(vb);
                uint32_t b1 = *(const uint32_t*)(vb + 8);
                mma16816(oacc[nf], pa, b0, b1);
            }
        }

        // drain prefetch into the other stage
        if (t < 15) {
            half* Kn = Ks + ((t + 1) & 1) * 4608;
            half* Vn = Vs + ((t + 1) & 1) * 4608;
            const half* kh = (const half*)&kpre0;
#pragma unroll
            for (int jj = 0; jj < 8; jj++) Kn[(jb + jj) * 72 + dK] = kh[jj];
            kh = (const half*)&kpre1;
#pragma unroll
            for (int jj = 0; jj < 8; jj++) Kn[(jb + 8 + jj) * 72 + dK] = kh[jj];
            *(uint4*)&Vn[dK * 72 + jb]     = vpre0;
            *(uint4*)&Vn[dK * 72 + jb + 8] = vpre1;
        }
        __syncthreads();
    }

    // row-sum reduction within quad, normalize, store
    l0 += __shfl_xor_sync(0xffffffffu, l0, 1);
    l0 += __shfl_xor_sync(0xffffffffu, l0, 2);
    l1 += __shfl_xor_sync(0xffffffffu, l1, 1);
    l1 += __shfl_xor_sync(0xffffffffu, l1, 2);
    float inv0 = 1.0f / l0, inv1 = 1.0f / l1;

    half* dst0 = g_o + ((size_t)(b * 1024 + ig)  * 512 + h * 64);
    half* dst1 = g_o + ((size_t)(b * 1024 + ig8) * 512 + h * 64);
#pragma unroll
    for (int nf = 0; nf < 8; nf++) {
        *(__half2*)(dst0 + nf * 8 + 2 * tig) = __floats2half2_rn(oacc[nf][0] * inv0, oacc[nf][1] * inv0);
        *(__half2*)(dst1 + nf * 8 + 2 * tig) = __floats2half2_rn(oacc[nf][2] * inv1, oacc[nf][3] * inv1);
    }
}

// ============================================================================
// Kernel 3: hardswish + output GEMM (fp16 wmma, 2-stage pipeline) + bias + BN.
// A = hswish(g_o)[p][c], B = W2[o][c] col_major -> acc (p,o).
// Dynamic smem: 2 stages x (As 128x40 | Bs 128x40) = 40960 B.
// ============================================================================
__global__ __launch_bounds__(256) void outproj_kernel(
    const float* __restrict__ W2, const float* __restrict__ b_out,
    const float* __restrict__ gam, const float* __restrict__ bet,
    const float* __restrict__ mu, const float* __restrict__ var,
    float* __restrict__ out)
{
    extern __shared__ char ps[];
    __shared__ float so[128], to[128], bo_s[128];
    __shared__ float Es[8][384];

    const int b  = blockIdx.z;
    const int o0 = blockIdx.y * 128;
    const int p0 = blockIdx.x * 128;
    const int tid  = threadIdx.x;
    const int warp = tid >> 5;
    const int lane = tid & 31;
    const half* Ob = g_o + (size_t)b * 1024 * 512;

    if (tid < 128) {
        int o = o0 + tid;
        float s = gam[o] * rsqrtf(var[o] + EPS);
        so[tid] = s;
        to[tid] = bet[o] - mu[o] * s;
        bo_s[tid] = b_out[o];
    }

    const int wp = (warp >> 1) * 32;
    const int wo = (warp & 1) * 64;

    wmma::fragment<wmma::accumulator, 16, 16, 16, float> acc[2][4];
#pragma unroll
    for (int i = 0; i < 2; i++)
#pragma unroll
        for (int j = 0; j < 4; j++) wmma::fill_fragment(acc[i][j], 0.0f);

    const int row = tid >> 1, kc0 = (tid & 1) * 16;

    uint4  areg[2];
    float4 breg[4];
    {
        const uint4* as = (const uint4*)(Ob + (size_t)(p0 + row) * 512 + kc0);
        areg[0] = as[0]; areg[1] = as[1];
        const float4* bs = (const float4*)(W2 + (size_t)(o0 + row) * 512 + kc0);
#pragma unroll
        for (int u = 0; u < 4; u++) breg[u] = bs[u];
    }
    {
        const half* hr = (const half*)areg;
        half2* ad = (half2*)(ps + (row * 40 + kc0) * 2);
        half2* bd = (half2*)(ps + 10240 + (row * 40 + kc0) * 2);
#pragma unroll
        for (int u = 0; u < 8; u++)
            ad[u] = __floats2half2_rn(hswish_f(__half2float(hr[2 * u])),
                                      hswish_f(__half2float(hr[2 * u + 1])));
#pragma unroll
        for (int u = 0; u < 4; u++) {
            bd[u * 2 + 0] = __floats2half2_rn(breg[u].x, breg[u].y);
            bd[u * 2 + 1] = __floats2half2_rn(breg[u].z, breg[u].w);
        }
    }
    __syncthreads();

    for (int kk = 0, s = 0; kk < 512; kk += 32, s ^= 1) {
        const bool more = (kk + 32 < 512);
        if (more) {
            const uint4* as = (const uint4*)(Ob + (size_t)(p0 + row) * 512 + kk + 32 + kc0);
            areg[0] = as[0]; areg[1] = as[1];
            const float4* bs = (const float4*)(W2 + (size_t)(o0 + row) * 512 + kk + 32 + kc0);
#pragma unroll
            for (int u = 0; u < 4; u++) breg[u] = bs[u];
        }
        half* As = (half*)(ps + s * 20480);
        half* Bs = (half*)(ps + s * 20480 + 10240);
#pragma unroll
        for (int ks = 0; ks < 32; ks += 16) {
            wmma::fragment<wmma::matrix_a, 16, 16, 16, half, wmma::row_major> a[2];
            wmma::load_matrix_sync(a[0], As + wp * 40 + ks, 40);
            wmma::load_matrix_sync(a[1], As + (wp + 16) * 40 + ks, 40);
#pragma unroll
            for (int nf = 0; nf < 4; nf++) {
                wmma::fragment<wmma::matrix_b, 16, 16, 16, half, wmma::col_major> bf;
                wmma::load_matrix_sync(bf, Bs + (wo + nf * 16) * 40 + ks, 40);
                wmma::mma_sync(acc[0][nf], a[0], bf, acc[0][nf]);
                wmma::mma_sync(acc[1][nf], a[1], bf, acc[1][nf]);
            }
        }
        if (more) {
            const half* hr = (const half*)areg;
            half2* ad = (half2*)(ps + (s ^ 1) * 20480 + (row * 40 + kc0) * 2);
            half2* bd = (half2*)(ps + (s ^ 1) * 20480 + 10240 + (row * 40 + kc0) * 2);
#pragma unroll
            for (int u = 0; u < 8; u++)
                ad[u] = __floats2half2_rn(hswish_f(__half2float(hr[2 * u])),
                                          hswish_f(__half2float(hr[2 * u + 1])));
#pragma unroll
            for (int u = 0; u < 4; u++) {
                bd[u * 2 + 0] = __floats2half2_rn(breg[u].x, breg[u].y);
                bd[u * 2 + 1] = __floats2half2_rn(breg[u].z, breg[u].w);
            }
        }
        __syncthreads();
    }

    // Epilogue
    float* es = &Es[warp][0];
#pragma unroll
    for (int mf = 0; mf < 2; mf++)
#pragma unroll
        for (int nf = 0; nf < 4; nf++) {
            wmma::store_matrix_sync(es, acc[mf][nf], 24, wmma::mem_col_major);
            __syncwarp();
            int r = lane >> 1, cb = (lane & 1) * 8;
            int o_l = wo + nf * 16 + r;
            int p_l = wp + mf * 16 + cb;
            float s = so[o_l], t = to[o_l], bb = bo_s[o_l];
            float* dst = out + (size_t)(b * 256 + o0 + o_l) * 1024 + p0 + p_l;
            const float* er = es + r * 24 + cb;
            float4 v0, v1;
            v0.x = (er[0] + bb) * s + t;  v0.y = (er[1] + bb) * s + t;
            v0.z = (er[2] + bb) * s + t;  v0.w = (er[3] + bb) * s + t;
            v1.x = (er[4] + bb) * s + t;  v1.y = (er[5] + bb) * s + t;
            v1.z = (er[6] + bb) * s + t;  v1.w = (er[7] + bb) * s + t;
            *(float4*)dst = v0;
            *(float4*)(dst + 4) = v1;
            __syncwarp();
        }
}

// ============================================================================
extern "C" void kernel_launch(void* const* d_in, const int* in_sizes, int n_in,
                              void* d_out, int out_size)
{
    const float* x    = (const float*)d_in[0];
    const float* wq   = (const float*)d_in[1];
    const float* gq   = (const float*)d_in[2];
    const float* bq   = (const float*)d_in[3];
    const float* mq   = (const float*)d_in[4];
    const float* vq   = (const float*)d_in[5];
    const float* wk   = (const float*)d_in[6];
    const float* gk   = (const float*)d_in[7];
    const float* bk   = (const float*)d_in[8];
    const float* mk   = (const float*)d_in[9];
    const float* vk   = (const float*)d_in[10];
    const float* wv   = (const float*)d_in[11];
    const float* gv   = (const float*)d_in[12];
    const float* bv   = (const float*)d_in[13];
    const float* mv   = (const float*)d_in[14];
    const float* vv   = (const float*)d_in[15];
    const float* emb  = (const float*)d_in[16];
    const float* w_o  = (const float*)d_in[17];
    const float* b_o  = (const float*)d_in[18];
    const float* go   = (const float*)d_in[19];
    const float* bo   = (const float*)d_in[20];
    const float* mo   = (const float*)d_in[21];
    const float* vo   = (const float*)d_in[22];
    // d_in[23] = pos_indices: recomputed on the fly in attn_kernel, unused.

    cudaFuncSetAttribute(proj_kernel,    cudaFuncAttributeMaxDynamicSharedMemorySize, 37888);
    cudaFuncSetAttribute(attn_kernel,    cudaFuncAttributeMaxDynamicSharedMemorySize, 59392);
    cudaFuncSetAttribute(outproj_kernel, cudaFuncAttributeMaxDynamicSharedMemorySize, 40960);

    proj_kernel<<<dim3(8, 4, 48), 256, 37888>>>(x, wq, wk, wv,
                                                gq, bq, mq, vq,
                                                gk, bk, mk, vk,
                                                gv, bv, mv, vv);
    attn_kernel<<<dim3(8, 128), 256, 59392>>>(emb);
    outproj_kernel<<<dim3(8, 2, 16), 256, 40960>>>(w_o, b_o, go, bo, mo, vo, (float*)d_out);
}

// round 12
// speedup vs baseline: 6.9947x; 1.5959x over previous
#include <cuda_runtime.h>
#include <cuda_fp16.h>
#include <mma.h>
#include <cstdint>

using namespace nvcuda;

#define EPS 1e-5f

// ---- scratch (static device globals; no allocation at runtime) ----
static __device__ half g_x16[16 * 256 * 1024];  // X converted to half [b][c][p]
static __device__ half g_wq16[512 * 256];
static __device__ half g_wk16[512 * 256];
static __device__ half g_wv16[512 * 256];
static __device__ half g_w216[256 * 512];
static __device__ half g_q[16 * 512 * 1024];    // [b, h*64+d, i]
static __device__ half g_k[16 * 512 * 1024];    // [b, h*64+d, j]
static __device__ half g_v[16 * 512 * 1024];    // [b, h*64+d, j]
static __device__ half g_o[16 * 1024 * 512];    // [b, i, h*64+d], hardswish applied

__device__ __forceinline__ float hswish_f(float x) {
    return x * __saturatef((x + 3.0f) * (1.0f / 6.0f));
}

__device__ __forceinline__ uint32_t packh2(float a, float b) {
    __half2 h = __floats2half2_rn(a, b);
    return *reinterpret_cast<uint32_t*>(&h);
}

__device__ __forceinline__ uint32_t smem_u32(const void* p) {
    return (uint32_t)__cvta_generic_to_shared(p);
}
__device__ __forceinline__ void cp16(uint32_t dst, const void* src) {
    asm volatile("cp.async.cg.shared.global [%0], [%1], 16;" :: "r"(dst), "l"(src));
}
__device__ __forceinline__ void cp_commit() { asm volatile("cp.async.commit_group;"); }
template<int N> __device__ __forceinline__ void cp_wait() {
    asm volatile("cp.async.wait_group %0;" :: "n"(N));
}
__device__ __forceinline__ void ldsm_x4(uint32_t& r0, uint32_t& r1, uint32_t& r2, uint32_t& r3, uint32_t a) {
    asm volatile("ldmatrix.sync.aligned.m8n8.x4.shared.b16 {%0,%1,%2,%3}, [%4];"
        : "=r"(r0), "=r"(r1), "=r"(r2), "=r"(r3) : "r"(a));
}
__device__ __forceinline__ void ldsm_x4_t(uint32_t& r0, uint32_t& r1, uint32_t& r2, uint32_t& r3, uint32_t a) {
    asm volatile("ldmatrix.sync.aligned.m8n8.x4.trans.shared.b16 {%0,%1,%2,%3}, [%4];"
        : "=r"(r0), "=r"(r1), "=r"(r2), "=r"(r3) : "r"(a));
}

// mma.sync m16n8k16 row.col f32.f16.f16.f32, accumulate in place
__device__ __forceinline__ void mma16816(float* d, const uint32_t* a, uint32_t b0, uint32_t b1) {
    asm volatile(
        "mma.sync.aligned.m16n8k16.row.col.f32.f16.f16.f32 "
        "{%0,%1,%2,%3}, {%4,%5,%6,%7}, {%8,%9}, {%0,%1,%2,%3};\n"
        : "+f"(d[0]), "+f"(d[1]), "+f"(d[2]), "+f"(d[3])
        : "r"(a[0]), "r"(a[1]), "r"(a[2]), "r"(a[3]), "r"(b0), "r"(b1));
}

// ============================================================================
// Kernel 0: convert fp32 inputs to fp16 globals (4 floats per thread).
// ============================================================================
__global__ __launch_bounds__(256) void convert_kernel(
    const float* __restrict__ X, const float* __restrict__ Wq,
    const float* __restrict__ Wk, const float* __restrict__ Wv,
    const float* __restrict__ W2)
{
    int i = blockIdx.x * 256 + threadIdx.x;   // float4 index
    const int NX = 1048576, NW = 32768;       // in float4 units
    const float* src; half* dst; int off;
    if (i < NX)                 { src = X;  dst = g_x16;  off = i; }
    else if (i < NX + NW)       { src = Wq; dst = g_wq16; off = i - NX; }
    else if (i < NX + 2 * NW)   { src = Wk; dst = g_wk16; off = i - NX - NW; }
    else if (i < NX + 3 * NW)   { src = Wv; dst = g_wv16; off = i - NX - 2 * NW; }
    else if (i < NX + 4 * NW)   { src = W2; dst = g_w216; off = i - NX - 3 * NW; }
    else return;
    float4 f = ((const float4*)src)[off];
    half2* d2 = (half2*)(dst + (size_t)off * 4);
    d2[0] = __floats2half2_rn(f.x, f.y);
    d2[1] = __floats2half2_rn(f.z, f.w);
}

// ============================================================================
// Kernel 1: fused Q/K/V projection GEMM (fp16 wmma, cp.async 3-stage) + BN.
// out[b,o,p] = bn(sum_c W[o,c] * X[b,c,p]).  Tile 128o x 128p, 256 thr.
// smem: 3 stages x (Ws 128x40 half = 10240B | Xs 32x136 half = 8704B) = 56832.
// ============================================================================
__global__ __launch_bounds__(256) void proj_kernel(
    const float* __restrict__ gq, const float* __restrict__ bq,
    const float* __restrict__ mq, const float* __restrict__ vq,
    const float* __restrict__ gk, const float* __restrict__ bk,
    const float* __restrict__ mk, const float* __restrict__ vk,
    const float* __restrict__ gv, const float* __restrict__ bv,
    const float* __restrict__ mv, const float* __restrict__ vv)
{
    extern __shared__ char ps[];
    __shared__ float so[128], to[128];
    __shared__ float Es[8][384];

    const int which = blockIdx.z >> 4;
    const int b     = blockIdx.z & 15;
    const half* W    = (which == 0) ? g_wq16 : (which == 1) ? g_wk16 : g_wv16;
    const float* gam = (which == 0) ? gq : (which == 1) ? gk : gv;
    const float* bet = (which == 0) ? bq : (which == 1) ? bk : bv;
    const float* mu  = (which == 0) ? mq : (which == 1) ? mk : mv;
    const float* var = (which == 0) ? vq : (which == 1) ? vk : vv;
    half* outbuf     = (which == 0) ? g_q : (which == 1) ? g_k : g_v;

    const int o0 = blockIdx.y * 128;
    const int p0 = blockIdx.x * 128;
    const int tid  = threadIdx.x;
    const int warp = tid >> 5;
    const int lane = tid & 31;
    const half* Xb = g_x16 + (size_t)b * 256 * 1024;

    if (tid < 128) {
        int o = o0 + tid;
        float s = gam[o] * rsqrtf(var[o] + EPS);
        so[tid] = s;
        to[tid] = bet[o] - mu[o] * s;
    }

    const uint32_t sm0 = smem_u32(ps);
    // chunk issue: stage stride 18944 B; Ws at +0 (stride 40), Xs at +10240 (stride 136)
    const int wc_o = tid >> 1, wc_k = (tid & 1) * 8;       // W: 128 rows x 2 chunks... (two per thread below)
    auto issue = [&](int t, int s) {
        int kk = t * 32;
        uint32_t base = sm0 + s * 18944;
#pragma unroll
        for (int u = 0; u < 2; u++) {
            int c = tid + u * 256;                  // 0..511
            int o = c >> 2, ko = (c & 3) * 8;
            cp16(base + (o * 40 + ko) * 2, W + (size_t)(o0 + o) * 256 + kk + ko);
            int kc = c >> 4, po = (c & 15) * 8;
            cp16(base + 10240 + (kc * 136 + po) * 2, Xb + (size_t)(kk + kc) * 1024 + p0 + po);
        }
    };
    (void)wc_o; (void)wc_k;

    const int wo = (warp >> 1) * 32;
    const int wp = (warp & 1) * 64;

    wmma::fragment<wmma::accumulator, 16, 16, 16, float> acc[2][4];
#pragma unroll
    for (int i = 0; i < 2; i++)
#pragma unroll
        for (int j = 0; j < 4; j++) wmma::fill_fragment(acc[i][j], 0.0f);

    issue(0, 0); cp_commit();
    issue(1, 1); cp_commit();

    for (int t = 0; t < 8; t++) {
        if (t < 7) cp_wait<1>(); else cp_wait<0>();
        __syncthreads();
        if (t + 2 < 8) { issue(t + 2, (t + 2) % 3); cp_commit(); }
        const half* Wst = (const half*)(ps + (t % 3) * 18944);
        const half* Xst = (const half*)(ps + (t % 3) * 18944 + 10240);
#pragma unroll
        for (int ks = 0; ks < 32; ks += 16) {
            wmma::fragment<wmma::matrix_a, 16, 16, 16, half, wmma::row_major> a[2];
            wmma::load_matrix_sync(a[0], Wst + wo * 40 + ks, 40);
            wmma::load_matrix_sync(a[1], Wst + (wo + 16) * 40 + ks, 40);
#pragma unroll
            for (int nf = 0; nf < 4; nf++) {
                wmma::fragment<wmma::matrix_b, 16, 16, 16, half, wmma::row_major> bf;
                wmma::load_matrix_sync(bf, Xst + ks * 136 + wp + nf * 16, 136);
                wmma::mma_sync(acc[0][nf], a[0], bf, acc[0][nf]);
                wmma::mma_sync(acc[1][nf], a[1], bf, acc[1][nf]);
            }
        }
    }
    __syncthreads();

    // Epilogue: BN, convert half, store [o][p]
    float* es = &Es[warp][0];
#pragma unroll
    for (int mf = 0; mf < 2; mf++)
#pragma unroll
        for (int nf = 0; nf < 4; nf++) {
            wmma::store_matrix_sync(es, acc[mf][nf], 24, wmma::mem_row_major);
            __syncwarp();
            int r = lane >> 1, cb = (lane & 1) * 8;
            int o_l = wo + mf * 16 + r;
            float s = so[o_l], t = to[o_l];
            union { uint4 u; half h[8]; } hb;
#pragma unroll
            for (int c = 0; c < 8; c++)
                hb.h[c] = __float2half(es[r * 24 + cb + c] * s + t);
            int o = o0 + o_l;
            int p = p0 + wp + nf * 16 + cb;
            *(uint4*)(outbuf + ((size_t)(b * 512 + o) * 1024 + p)) = hb.u;
            __syncwarp();
        }
}

// ============================================================================
// Kernel 2: attention, mma.sync + ldmatrix, cp.async 3-stage K/V, in-register
// streaming softmax (no max-sub, |S|<~6), hardswish fused into epilogue.
// No transposes anywhere: Q/K via ldmatrix.trans from [d][pos], V non-trans.
// smem: Qs 64x136 (17408) | Ks 3x64x72 (27648) | Vs 3x64x72 (27648) |
//       semb 4096  => 76800 B
// ============================================================================
__global__ __launch_bounds__(256) void attn_kernel(const float* __restrict__ emb)
{
    extern __shared__ char smc[];
    half*  Qs   = (half*)(smc);
    half*  Ks   = (half*)(smc + 17408);
    half*  Vs   = (half*)(smc + 45056);
    float* semb = (float*)(smc + 72704);

    const int bh = blockIdx.y;
    const int b = bh >> 3, h = bh & 7;
    const int i0 = blockIdx.x * 128;
    const int tid  = threadIdx.x;
    const int warp = tid >> 5;
    const int lane = tid & 31;
    const int g    = lane >> 2;
    const int tig  = lane & 3;

    const half* Qg = g_q + (size_t)(b * 512 + h * 64) * 1024;
    const half* Kg = g_k + (size_t)(b * 512 + h * 64) * 1024;
    const half* Vg = g_v + (size_t)(b * 512 + h * 64) * 1024;

    const uint32_t qsm = smem_u32(Qs);
    const uint32_t ksm = smem_u32(Ks);
    const uint32_t vsm = smem_u32(Vs);

    for (int i = tid; i < 1024; i += 256)
        semb[i] = emb[i * 8 + h] * 8.0f;

    // Q: 64 d-rows x 128 i, stride 136 (natural [d][i], no transpose)
#pragma unroll
    for (int u = 0; u < 4; u++) {
        int c = tid + u * 256;
        int d = c >> 4, io = (c & 15) * 8;
        cp16(qsm + (d * 136 + io) * 2, Qg + (size_t)d * 1024 + i0 + io);
    }

    auto issue_kv = [&](int t, int s) {
        int j0 = t * 64;
        uint32_t kb = ksm + s * 9216, vb = vsm + s * 9216;
#pragma unroll
        for (int u = 0; u < 2; u++) {
            int c = tid + u * 256;
            int d = c >> 3, jo = (c & 7) * 8;
            cp16(kb + (d * 72 + jo) * 2, Kg + (size_t)d * 1024 + j0 + jo);
            cp16(vb + (d * 72 + jo) * 2, Vg + (size_t)d * 1024 + j0 + jo);
        }
    };

    issue_kv(0, 0); cp_commit();   // G0 (with Q)
    issue_kv(1, 1); cp_commit();   // G1
    cp_wait<1>();                  // G0 done
    __syncthreads();

    // Q A-fragments via ldmatrix.trans from [d][i]
    const int iw = warp * 16;
    const int l = lane;
    const int qRow = (l & 7) + (l >> 4) * 8;            // d-row within 16
    const int qCol = iw + ((l >> 3) & 1) * 8;           // i (+8 for a1/a3)
    uint32_t qa[4][4];
#pragma unroll
    for (int dk = 0; dk < 4; dk++)
        ldsm_x4_t(qa[dk][0], qa[dk][1], qa[dk][2], qa[dk][3],
                  qsm + ((dk * 16 + qRow) * 136 + qCol) * 2);

    const int kRow  = (l & 7) + ((l >> 3) & 1) * 8;     // d within 16 (b0/b1)
    const int kCol8 = (l >> 4) * 8;                     // j +8 for second nf
    const int vRow  = (l & 7) + (l >> 4) * 8;           // d (n-dim)
    const int vCol8 = ((l >> 3) & 1) * 8;               // j +8 for b1

    const int ig  = i0 + iw + g;
    const int ig8 = ig + 8;
    const int xi0 = ig >> 5,  yi0 = ig & 31;
    const int xi8 = ig8 >> 5, yi8 = ig8 & 31;

    float oacc[8][4];
#pragma unroll
    for (int nf = 0; nf < 8; nf++)
#pragma unroll
        for (int c = 0; c < 4; c++) oacc[nf][c] = 0.0f;
    float l0 = 0.0f, l1 = 0.0f;

    for (int t = 0; t < 16; t++) {
        if (t < 15) cp_wait<1>(); else cp_wait<0>();
        __syncthreads();
        if (t + 2 < 16) { issue_kv(t + 2, (t + 2) % 3); cp_commit(); }

        const uint32_t kb = ksm + (t % 3) * 9216;
        const uint32_t vb = vsm + (t % 3) * 9216;

        // S = Q K^T (K via ldmatrix.trans from natural [d][j])
        float sacc[8][4];
#pragma unroll
        for (int nf = 0; nf < 8; nf++)
#pragma unroll
            for (int c = 0; c < 4; c++) sacc[nf][c] = 0.0f;
#pragma unroll
        for (int dk = 0; dk < 4; dk++) {
#pragma unroll
            for (int nfp = 0; nfp < 4; nfp++) {
                uint32_t b0a, b1a, b0b, b1b;
                ldsm_x4_t(b0a, b1a, b0b, b1b,
                          kb + ((dk * 16 + kRow) * 72 + nfp * 16 + kCol8) * 2);
                mma16816(sacc[2 * nfp],     qa[dk], b0a, b1a);
                mma16816(sacc[2 * nfp + 1], qa[dk], b0b, b1b);
            }
        }

        // bias + exp, in registers
        const int jt = t * 64 + 2 * tig;
#pragma unroll
        for (int nf = 0; nf < 8; nf++) {
            int j0e = jt + nf * 8;
            int xj0 = j0e >> 5,       yj0 = j0e & 31;
            int xj1 = (j0e + 1) >> 5, yj1 = (j0e + 1) & 31;
            float bi00 = semb[abs(xi0 - xj0) * 32 + abs(yi0 - yj0)];
            float bi01 = semb[abs(xi0 - xj1) * 32 + abs(yi0 - yj1)];
            float bi10 = semb[abs(xi8 - xj0) * 32 + abs(yi8 - yj0)];
            float bi11 = semb[abs(xi8 - xj1) * 32 + abs(yi8 - yj1)];
            float e0 = __expf(fmaf(sacc[nf][0], 0.125f, bi00));
            float e1 = __expf(fmaf(sacc[nf][1], 0.125f, bi01));
            float e2 = __expf(fmaf(sacc[nf][2], 0.125f, bi10));
            float e3 = __expf(fmaf(sacc[nf][3], 0.125f, bi11));
            l0 += e0 + e1;
            l1 += e2 + e3;
            sacc[nf][0] = e0; sacc[nf][1] = e1;
            sacc[nf][2] = e2; sacc[nf][3] = e3;
        }

        // O += P V (V non-trans ldmatrix from natural [d][j])
#pragma unroll
        for (int kf = 0; kf < 4; kf++) {
            uint32_t pa[4];
            pa[0] = packh2(sacc[2 * kf][0],     sacc[2 * kf][1]);
            pa[1] = packh2(sacc[2 * kf][2],     sacc[2 * kf][3]);
            pa[2] = packh2(sacc[2 * kf + 1][0], sacc[2 * kf + 1][1]);
            pa[3] = packh2(sacc[2 * kf + 1][2], sacc[2 * kf + 1][3]);
#pragma unroll
            for (int nfp = 0; nfp < 4; nfp++) {
                uint32_t v0a, v1a, v0b, v1b;
                ldsm_x4(v0a, v1a, v0b, v1b,
                        vb + ((nfp * 16 + vRow) * 72 + kf * 16 + vCol8) * 2);
                mma16816(oacc[2 * nfp],     pa, v0a, v1a);
                mma16816(oacc[2 * nfp + 1], pa, v0b, v1b);
            }
        }
    }

    // row-sum reduction within quad, normalize, hardswish, store
    l0 += __shfl_xor_sync(0xffffffffu, l0, 1);
    l0 += __shfl_xor_sync(0xffffffffu, l0, 2);
    l1 += __shfl_xor_sync(0xffffffffu, l1, 1);
    l1 += __shfl_xor_sync(0xffffffffu, l1, 2);
    float inv0 = 1.0f / l0, inv1 = 1.0f / l1;

    half* dst0 = g_o + ((size_t)(b * 1024 + ig)  * 512 + h * 64);
    half* dst1 = g_o + ((size_t)(b * 1024 + ig8) * 512 + h * 64);
#pragma unroll
    for (int nf = 0; nf < 8; nf++) {
        *(__half2*)(dst0 + nf * 8 + 2 * tig) =
            __floats2half2_rn(hswish_f(oacc[nf][0] * inv0), hswish_f(oacc[nf][1] * inv0));
        *(__half2*)(dst1 + nf * 8 + 2 * tig) =
            __floats2half2_rn(hswish_f(oacc[nf][2] * inv1), hswish_f(oacc[nf][3] * inv1));
    }
}

// ============================================================================
// Kernel 3: output GEMM (pure fp16, cp.async 3-stage) + bias + BN.
// g_o already holds hardswish(attn_out).  A=[p][c], B=W2h[o][c] col -> (p,o).
// smem: 3 stages x (As 10240 + Bs 10240) = 61440 B.
// ============================================================================
__global__ __launch_bounds__(256) void outproj_kernel(
    const float* __restrict__ b_out,
    const float* __restrict__ gam, const float* __restrict__ bet,
    const float* __restrict__ mu, const float* __restrict__ var,
    float* __restrict__ out)
{
    extern __shared__ char ps[];
    __shared__ float so[128], to[128], bo_s[128];
    __shared__ float Es[8][384];

    const int b  = blockIdx.z;
    const int o0 = blockIdx.y * 128;
    const int p0 = blockIdx.x * 128;
    const int tid  = threadIdx.x;
    const int warp = tid >> 5;
    const int lane = tid & 31;
    const half* Ob = g_o + (size_t)b * 1024 * 512;

    if (tid < 128) {
        int o = o0 + tid;
        float s = gam[o] * rsqrtf(var[o] + EPS);
        so[tid] = s;
        to[tid] = bet[o] - mu[o] * s;
        bo_s[tid] = b_out[o];
    }

    const uint32_t sm0 = smem_u32(ps);
    auto issue = [&](int t, int s) {
        int kk = t * 32;
        uint32_t base = sm0 + s * 20480;
#pragma unroll
        for (int u = 0; u < 2; u++) {
            int c = tid + u * 256;
            int r = c >> 2, ko = (c & 3) * 8;
            cp16(base + (r * 40 + ko) * 2, Ob + (size_t)(p0 + r) * 512 + kk + ko);
            cp16(base + 10240 + (r * 40 + ko) * 2, g_w216 + (size_t)(o0 + r) * 512 + kk + ko);
        }
    };

    const int wp = (warp >> 1) * 32;
    const int wo = (warp & 1) * 64;

    wmma::fragment<wmma::accumulator, 16, 16, 16, float> acc[2][4];
#pragma unroll
    for (int i = 0; i < 2; i++)
#pragma unroll
        for (int j = 0; j < 4; j++) wmma::fill_fragment(acc[i][j], 0.0f);

    issue(0, 0); cp_commit();
    issue(1, 1); cp_commit();

    for (int t = 0; t < 16; t++) {
        if (t < 15) cp_wait<1>(); else cp_wait<0>();
        __syncthreads();
        if (t + 2 < 16) { issue(t + 2, (t + 2) % 3); cp_commit(); }
        const half* As = (const half*)(ps + (t % 3) * 20480);
        const half* Bs = (const half*)(ps + (t % 3) * 20480 + 10240);
#pragma unroll
        for (int ks = 0; ks < 32; ks += 16) {
            wmma::fragment<wmma::matrix_a, 16, 16, 16, half, wmma::row_major> a[2];
            wmma::load_matrix_sync(a[0], As + wp * 40 + ks, 40);
            wmma::load_matrix_sync(a[1], As + (wp + 16) * 40 + ks, 40);
#pragma unroll
            for (int nf = 0; nf < 4; nf++) {
                wmma::fragment<wmma::matrix_b, 16, 16, 16, half, wmma::col_major> bf;
                wmma::load_matrix_sync(bf, Bs + (wo + nf * 16) * 40 + ks, 40);
                wmma::mma_sync(acc[0][nf], a[0], bf, acc[0][nf]);
                wmma::mma_sync(acc[1][nf], a[1], bf, acc[1][nf]);
            }
        }
    }
    __syncthreads();

    // Epilogue: acc (m=p, n=o); col-major store -> es[o][p], BN per o, fp32 out
    float* es = &Es[warp][0];
#pragma unroll
    for (int mf = 0; mf < 2; mf++)
#pragma unroll
        for (int nf = 0; nf < 4; nf++) {
            wmma::store_matrix_sync(es, acc[mf][nf], 24, wmma::mem_col_major);
            __syncwarp();
            int r = lane >> 1, cb = (lane & 1) * 8;
            int o_l = wo + nf * 16 + r;
            int p_l = wp + mf * 16 + cb;
            float s = so[o_l], t = to[o_l], bb = bo_s[o_l];
            float* dst = out + (size_t)(b * 256 + o0 + o_l) * 1024 + p0 + p_l;
            const float* er = es + r * 24 + cb;
            float4 v0, v1;
            v0.x = (er[0] + bb) * s + t;  v0.y = (er[1] + bb) * s + t;
            v0.z = (er[2] + bb) * s + t;  v0.w = (er[3] + bb) * s + t;
            v1.x = (er[4] + bb) * s + t;  v1.y = (er[5] + bb) * s + t;
            v1.z = (er[6] + bb) * s + t;  v1.w = (er[7] + bb) * s + t;
            *(float4*)dst = v0;
            *(float4*)(dst + 4) = v1;
            __syncwarp();
        }
}

// ============================================================================
extern "C" void kernel_launch(void* const* d_in, const int* in_sizes, int n_in,
                              void* d_out, int out_size)
{
    const float* x    = (const float*)d_in[0];
    const float* wq   = (const float*)d_in[1];
    const float* gq   = (const float*)d_in[2];
    const float* bq   = (const float*)d_in[3];
    const float* mq   = (const float*)d_in[4];
    const float* vq   = (const float*)d_in[5];
    const float* wk   = (const float*)d_in[6];
    const float* gk   = (const float*)d_in[7];
    const float* bk   = (const float*)d_in[8];
    const float* mk   = (const float*)d_in[9];
    const float* vk   = (const float*)d_in[10];
    const float* wv   = (const float*)d_in[11];
    const float* gv   = (const float*)d_in[12];
    const float* bv   = (const float*)d_in[13];
    const float* mv   = (const float*)d_in[14];
    const float* vv   = (const float*)d_in[15];
    const float* emb  = (const float*)d_in[16];
    const float* w_o  = (const float*)d_in[17];
    const float* b_o  = (const float*)d_in[18];
    const float* go   = (const float*)d_in[19];
    const float* bo   = (const float*)d_in[20];
    const float* mo   = (const float*)d_in[21];
    const float* vo   = (const float*)d_in[22];
    // d_in[23] = pos_indices: recomputed on the fly in attn_kernel, unused.

    cudaFuncSetAttribute(proj_kernel,    cudaFuncAttributeMaxDynamicSharedMemorySize, 56832);
    cudaFuncSetAttribute(attn_kernel,    cudaFuncAttributeMaxDynamicSharedMemorySize, 76800);
    cudaFuncSetAttribute(outproj_kernel, cudaFuncAttributeMaxDynamicSharedMemorySize, 61440);

    convert_kernel<<<4608, 256>>>(x, wq, wk, wv, w_o);
    proj_kernel<<<dim3(8, 4, 48), 256, 56832>>>(gq, bq, mq, vq,
                                                gk, bk, mk, vk,
                                                gv, bv, mv, vv);
    attn_kernel<<<dim3(8, 128), 256, 76800>>>(emb);
    outproj_kernel<<<dim3(8, 2, 16), 256, 61440>>>(b_o, go, bo, mo, vo, (float*)d_out);
}